// round 1
// baseline (speedup 1.0000x reference)
#include <cuda_runtime.h>
#include <cuda_bf16.h>
#include <math.h>

// ---------------------------------------------------------------------------
// Problem constants
// ---------------------------------------------------------------------------
#define BSZ     2
#define LSEQ    1024
#define DMODEL  1024
#define DINNER  2048
#define DSTATE  16
#define DTRANK  64
#define DCONV   4
#define MROWS   (BSZ * LSEQ)      // 2048
#define NXZ     (2 * DINNER)      // 4096
#define NDBC    (DTRANK + 2*DSTATE) // 96
#define SPLITK_XPROJ 8
#define SPLITK_OPROJ 2

// ---------------------------------------------------------------------------
// Scratch (static device memory; no allocations allowed)
// ---------------------------------------------------------------------------
__device__ float g_xz[MROWS * NXZ];                       // 32 MB  (xs | z)
__device__ float g_xsc[MROWS * DINNER];                   // 16 MB  conv+silu output
__device__ float g_dbc_part[SPLITK_XPROJ * MROWS * NDBC]; // 6 MB
__device__ float g_dbc[MROWS * NDBC];                     // 0.75 MB
__device__ float g_delta[MROWS * DINNER];                 // 16 MB
__device__ float g_y[MROWS * DINNER];                     // 16 MB  gated scan output
__device__ float g_opart[SPLITK_OPROJ * MROWS * DMODEL];  // 16 MB

// ---------------------------------------------------------------------------
// Generic 128x128x8 SGEMM, C[m,n] = sum_k A[m,k] * B[n,k]   (both K-contiguous)
// grid = (ceil(N/128), M/128, nSplit). blockIdx.z picks K-chunk and writes to
// C + z*M*ldc (deterministic split-K; reduced by a separate kernel).
// EPI: 0 = plain store, 1 = softplus(x + bias[col]).
// Requires: M % 128 == 0, K % 8 == 0, rows of A/B 16B-aligned (lda/ldb % 4 == 0).
// ---------------------------------------------------------------------------
template<int EPI>
__global__ void __launch_bounds__(256, 2) sgemm128(
    const float* __restrict__ A, const float* __restrict__ B,
    float* __restrict__ C, int M, int N, int K,
    int lda, int ldb, int ldc, int kChunk,
    const float* __restrict__ bias)
{
    __shared__ float As[8][128];
    __shared__ float Bs[8][128];

    const int tid = threadIdx.x;
    const int bm = blockIdx.y * 128;
    const int bn = blockIdx.x * 128;
    int kBegin = blockIdx.z * kChunk;
    int kEnd   = kBegin + kChunk; if (kEnd > K) kEnd = K;
    C += (size_t)blockIdx.z * (size_t)M * (size_t)ldc;

    const int ar = tid >> 1;          // 0..127  row within tile for loads
    const int ac = (tid & 1) * 4;     // 0 or 4  col within 8-wide K slab
    const int ty = tid >> 4;          // 0..15
    const int tx = tid & 15;          // 0..15

    float acc[8][8];
#pragma unroll
    for (int i = 0; i < 8; i++)
#pragma unroll
        for (int j = 0; j < 8; j++) acc[i][j] = 0.f;

    const float* Aptr = A + (size_t)(bm + ar) * lda + ac;
    const int brow = bn + ar;
    const float* Bptr = B + (size_t)brow * ldb + ac;
    const bool bvalid = (brow < N);

    for (int k0 = kBegin; k0 < kEnd; k0 += 8) {
        float4 av = *(const float4*)(Aptr + k0);
        float4 bv = make_float4(0.f, 0.f, 0.f, 0.f);
        if (bvalid) bv = *(const float4*)(Bptr + k0);

        __syncthreads();
        As[ac + 0][ar] = av.x; As[ac + 1][ar] = av.y;
        As[ac + 2][ar] = av.z; As[ac + 3][ar] = av.w;
        Bs[ac + 0][ar] = bv.x; Bs[ac + 1][ar] = bv.y;
        Bs[ac + 2][ar] = bv.z; Bs[ac + 3][ar] = bv.w;
        __syncthreads();

#pragma unroll
        for (int kk = 0; kk < 8; kk++) {
            float a[8], b[8];
#pragma unroll
            for (int i = 0; i < 8; i++) a[i] = As[kk][ty * 8 + i];
#pragma unroll
            for (int j = 0; j < 8; j++) b[j] = Bs[kk][tx * 8 + j];
#pragma unroll
            for (int i = 0; i < 8; i++)
#pragma unroll
                for (int j = 0; j < 8; j++)
                    acc[i][j] = fmaf(a[i], b[j], acc[i][j]);
        }
    }

#pragma unroll
    for (int i = 0; i < 8; i++) {
        const int row = bm + ty * 8 + i;
#pragma unroll
        for (int j = 0; j < 8; j++) {
            const int col = bn + tx * 8 + j;
            if (col < N) {
                float v = acc[i][j];
                if (EPI == 1) {
                    v += bias[col];
                    // stable softplus: max(x,0) + log1p(exp(-|x|))
                    v = fmaxf(v, 0.f) + log1pf(__expf(-fabsf(v)));
                }
                C[(size_t)row * ldc + col] = v;
            }
        }
    }
}

// ---------------------------------------------------------------------------
// Depthwise causal conv (k=4) + bias + SiLU.  Reads the xs half of g_xz.
// ---------------------------------------------------------------------------
__global__ void conv_silu_kernel(const float* __restrict__ xz,
                                 const float* __restrict__ cw,
                                 const float* __restrict__ cb,
                                 float* __restrict__ xsc)
{
    const int idx = blockIdx.x * blockDim.x + threadIdx.x;
    if (idx >= MROWS * DINNER) return;
    const int d = idx & (DINNER - 1);
    const int m = idx >> 11;
    const int l = m & (LSEQ - 1);

    const float w0 = cw[d * 4 + 0], w1 = cw[d * 4 + 1];
    const float w2 = cw[d * 4 + 2], w3 = cw[d * 4 + 3];
    const float* p = xz + (size_t)m * NXZ + d;

    float acc = cb[d] + w3 * p[0];
    if (l >= 1) acc = fmaf(w2, p[-NXZ],     acc);
    if (l >= 2) acc = fmaf(w1, p[-2 * NXZ], acc);
    if (l >= 3) acc = fmaf(w0, p[-3 * NXZ], acc);

    xsc[idx] = acc / (1.f + __expf(-acc));   // SiLU
}

// ---------------------------------------------------------------------------
// Split-K reductions
// ---------------------------------------------------------------------------
__global__ void reduce_dbc_kernel(const float* __restrict__ part,
                                  float* __restrict__ out)
{
    const int idx = blockIdx.x * blockDim.x + threadIdx.x;
    if (idx >= MROWS * NDBC) return;
    float s = 0.f;
#pragma unroll
    for (int j = 0; j < SPLITK_XPROJ; j++)
        s += part[(size_t)j * MROWS * NDBC + idx];
    out[idx] = s;
}

__global__ void reduce_out_kernel(const float* __restrict__ part,
                                  float* __restrict__ out)
{
    const int idx = blockIdx.x * blockDim.x + threadIdx.x;
    if (idx >= MROWS * DMODEL) return;
    out[idx] = part[idx] + part[(size_t)MROWS * DMODEL + idx];
}

// ---------------------------------------------------------------------------
// Selective scan: 16 lanes per (b,d) channel, one lane per state n.
// Fuses y += D*xs  and  out = y * silu(z).
// ---------------------------------------------------------------------------
__global__ void scan_kernel(const float* __restrict__ delta,
                            const float* __restrict__ xsc,
                            const float* __restrict__ dbc,
                            const float* __restrict__ xz,
                            const float* __restrict__ A_log,
                            const float* __restrict__ Dp,
                            float* __restrict__ y)
{
    const int gt = blockIdx.x * blockDim.x + threadIdx.x;
    const int ch = gt >> 4;                  // channel = b*DINNER + d
    if (ch >= BSZ * DINNER) return;
    const int n = threadIdx.x & 15;          // state index
    const int b = ch >> 11;
    const int d = ch & (DINNER - 1);

    const float An = -__expf(A_log[d * DSTATE + n]);
    const float Dd = Dp[d];

    const float* drow  = delta + (size_t)b * LSEQ * DINNER + d;
    const float* xrow  = xsc   + (size_t)b * LSEQ * DINNER + d;
    const float* zrow  = xz    + (size_t)b * LSEQ * NXZ + DINNER + d;
    const float* bcrow = dbc   + (size_t)b * LSEQ * NDBC;
    float*       yrow  = y     + (size_t)b * LSEQ * DINNER + d;

    float h = 0.f;
    for (int l = 0; l < LSEQ; l++) {
        const float dl = drow[(size_t)l * DINNER];
        const float xv = xrow[(size_t)l * DINNER];
        const float Bv = bcrow[l * NDBC + DTRANK + n];
        const float Cv = bcrow[l * NDBC + DTRANK + DSTATE + n];

        const float dA = __expf(dl * An);
        h = fmaf(dA, h, dl * xv * Bv);

        float part = h * Cv;
        part += __shfl_xor_sync(0xffffffffu, part, 8, 16);
        part += __shfl_xor_sync(0xffffffffu, part, 4, 16);
        part += __shfl_xor_sync(0xffffffffu, part, 2, 16);
        part += __shfl_xor_sync(0xffffffffu, part, 1, 16);

        if (n == 0) {
            const float yv = part + Dd * xv;
            const float zv = zrow[(size_t)l * NXZ];
            const float sz = zv / (1.f + __expf(-zv));
            yrow[(size_t)l * DINNER] = yv * sz;
        }
    }
}

// ---------------------------------------------------------------------------
// Launch
// ---------------------------------------------------------------------------
extern "C" void kernel_launch(void* const* d_in, const int* in_sizes, int n_in,
                              void* d_out, int out_size)
{
    const float* x         = (const float*)d_in[0];
    const float* in_proj_w = (const float*)d_in[1];
    const float* conv_w    = (const float*)d_in[2];
    const float* conv_b    = (const float*)d_in[3];
    const float* x_proj_w  = (const float*)d_in[4];
    const float* dt_proj_w = (const float*)d_in[5];
    const float* dt_proj_b = (const float*)d_in[6];
    const float* A_log     = (const float*)d_in[7];
    const float* Dvec      = (const float*)d_in[8];
    const float* out_proj_w= (const float*)d_in[9];
    float* out = (float*)d_out;

    float *xz, *xsc, *dbc_part, *dbc, *delta, *yb, *opart;
    cudaGetSymbolAddress((void**)&xz,       g_xz);
    cudaGetSymbolAddress((void**)&xsc,      g_xsc);
    cudaGetSymbolAddress((void**)&dbc_part, g_dbc_part);
    cudaGetSymbolAddress((void**)&dbc,      g_dbc);
    cudaGetSymbolAddress((void**)&delta,    g_delta);
    cudaGetSymbolAddress((void**)&yb,       g_y);
    cudaGetSymbolAddress((void**)&opart,    g_opart);

    // 1) xz = x @ in_proj_w^T     (2048 x 4096, K=1024)
    {
        dim3 grid(NXZ / 128, MROWS / 128, 1);
        sgemm128<0><<<grid, 256>>>(x, in_proj_w, xz,
                                   MROWS, NXZ, DMODEL,
                                   DMODEL, DMODEL, NXZ, DMODEL, nullptr);
    }

    // 2) depthwise conv + bias + silu -> xsc
    {
        int n = MROWS * DINNER;
        conv_silu_kernel<<<(n + 255) / 256, 256>>>(xz, conv_w, conv_b, xsc);
    }

    // 3) dbc = xsc @ x_proj_w^T   (2048 x 96, K=2048), split-K=8
    {
        dim3 grid(1, MROWS / 128, SPLITK_XPROJ);
        sgemm128<0><<<grid, 256>>>(xsc, x_proj_w, dbc_part,
                                   MROWS, NDBC, DINNER,
                                   DINNER, DINNER, NDBC, DINNER / SPLITK_XPROJ,
                                   nullptr);
        int n = MROWS * NDBC;
        reduce_dbc_kernel<<<(n + 255) / 256, 256>>>(dbc_part, dbc);
    }

    // 4) delta = softplus(dbc[:, :64] @ dt_proj_w^T + dt_proj_b)  (2048 x 2048, K=64)
    {
        dim3 grid(DINNER / 128, MROWS / 128, 1);
        sgemm128<1><<<grid, 256>>>(dbc, dt_proj_w, delta,
                                   MROWS, DINNER, DTRANK,
                                   NDBC, DTRANK, DINNER, DTRANK, dt_proj_b);
    }

    // 5) selective scan (+ D*xs, * silu(z)) -> yb
    {
        int threads = BSZ * DINNER * DSTATE;   // 65536
        scan_kernel<<<threads / 256, 256>>>(delta, xsc, dbc, xz, A_log, Dvec, yb);
    }

    // 6) out = yb @ out_proj_w^T  (2048 x 1024, K=2048), split-K=2
    {
        dim3 grid(DMODEL / 128, MROWS / 128, SPLITK_OPROJ);
        sgemm128<0><<<grid, 256>>>(yb, out_proj_w, opart,
                                   MROWS, DMODEL, DINNER,
                                   DINNER, DINNER, DMODEL, DINNER / SPLITK_OPROJ,
                                   nullptr);
        int n = MROWS * DMODEL;
        reduce_out_kernel<<<(n + 255) / 256, 256>>>(opart, out);
    }
}

// round 2
// speedup vs baseline: 1.4596x; 1.4596x over previous
#include <cuda_runtime.h>
#include <cuda_bf16.h>
#include <math.h>

// ---------------------------------------------------------------------------
// Problem constants
// ---------------------------------------------------------------------------
#define BSZ     2
#define LSEQ    1024
#define DMODEL  1024
#define DINNER  2048
#define DSTATE  16
#define DTRANK  64
#define DCONV   4
#define MROWS   (BSZ * LSEQ)        // 2048
#define NXZ     (2 * DINNER)        // 4096
#define NDBC    (DTRANK + 2*DSTATE) // 96
#define SPLITK_XPROJ 8
#define SPLITK_OPROJ 2

// ---------------------------------------------------------------------------
// Scratch (static device memory; no allocations allowed)
// ---------------------------------------------------------------------------
__device__ float g_xz[MROWS * NXZ];                       // (xs | z)
__device__ float g_xsc[MROWS * DINNER];                   // conv+silu output
__device__ float g_dbc_part[SPLITK_XPROJ * MROWS * NDBC];
__device__ float g_dbc[MROWS * NDBC];
__device__ float g_delta[MROWS * DINNER];
__device__ float g_y[MROWS * DINNER];                     // gated scan output
__device__ float g_opart[SPLITK_OPROJ * MROWS * DMODEL];

// ---------------------------------------------------------------------------
// TF32 helpers
// ---------------------------------------------------------------------------
__device__ __forceinline__ unsigned f2tf32(float x) {
    unsigned r;
    asm("cvt.rna.tf32.f32 %0, %1;" : "=r"(r) : "f"(x));
    return r;
}

__device__ __forceinline__ void mma_m16n8k8_tf32(float c[4], const unsigned a[4],
                                                 const unsigned b[2]) {
    asm volatile(
        "mma.sync.aligned.m16n8k8.row.col.f32.tf32.tf32.f32 "
        "{%0,%1,%2,%3}, {%4,%5,%6,%7}, {%8,%9}, {%0,%1,%2,%3};\n"
        : "+f"(c[0]), "+f"(c[1]), "+f"(c[2]), "+f"(c[3])
        : "r"(a[0]), "r"(a[1]), "r"(a[2]), "r"(a[3]), "r"(b[0]), "r"(b[1]));
}

// ---------------------------------------------------------------------------
// TF32 tensor-core GEMM: C[m,n] = sum_k A[m,k] * B[n,k] (both K-contiguous).
// CTA tile 128x128, K-slab 16, 8 warps (4M x 2N), warp tile 32x64.
// grid = (N/128, M/128, nSplit); blockIdx.z takes K-chunk, writes C + z*M*ldc.
// Requires M%128==0, kChunk%16==0, lda/ldb%4==0.
// ---------------------------------------------------------------------------
__global__ void __launch_bounds__(256, 2) tgemm_tf32(
    const float* __restrict__ A, const float* __restrict__ B,
    float* __restrict__ C, int M, int N, int K,
    int lda, int ldb, int ldc, int kChunk)
{
    // [row][20] padding: fragment gathers (banks (20*r+q)%32) are conflict-free
    __shared__ unsigned As[128][20];
    __shared__ unsigned Bs[128][20];

    const int tid = threadIdx.x;
    const int bm = blockIdx.y * 128;
    const int bn = blockIdx.x * 128;
    int kBegin = blockIdx.z * kChunk;
    int kEnd   = kBegin + kChunk; if (kEnd > K) kEnd = K;
    C += (size_t)blockIdx.z * (size_t)M * (size_t)ldc;

    const int lr = tid >> 1;          // 0..127: tile row handled by this thread
    const int lc = (tid & 1) * 8;     // 0 or 8: k-offset within 16-slab

    const float* Ap = A + (size_t)(bm + lr) * lda + lc;
    const int bnrow = bn + lr;
    const bool bok = (bnrow < N);
    const float* Bp = B + (size_t)(bok ? bnrow : 0) * ldb + lc;

    const int w = tid >> 5, lane = tid & 31;
    const int wm = (w & 3) * 32;      // warp M offset
    const int wn = (w >> 2) * 64;     // warp N offset
    const int q = lane & 3;           // thread-in-group
    const int r = lane >> 2;          // group id

    float acc[2][8][4];
#pragma unroll
    for (int i = 0; i < 2; i++)
#pragma unroll
        for (int j = 0; j < 8; j++)
#pragma unroll
            for (int t = 0; t < 4; t++) acc[i][j][t] = 0.f;

    float4 ra0, ra1, rb0, rb1;
    // prefetch first slab
    ra0 = *(const float4*)(Ap + kBegin);
    ra1 = *(const float4*)(Ap + kBegin + 4);
    if (bok) {
        rb0 = *(const float4*)(Bp + kBegin);
        rb1 = *(const float4*)(Bp + kBegin + 4);
    } else {
        rb0 = rb1 = make_float4(0.f, 0.f, 0.f, 0.f);
    }

    for (int k0 = kBegin; k0 < kEnd; k0 += 16) {
        __syncthreads();
        {
            uint4 ua0 = make_uint4(f2tf32(ra0.x), f2tf32(ra0.y), f2tf32(ra0.z), f2tf32(ra0.w));
            uint4 ua1 = make_uint4(f2tf32(ra1.x), f2tf32(ra1.y), f2tf32(ra1.z), f2tf32(ra1.w));
            uint4 ub0 = make_uint4(f2tf32(rb0.x), f2tf32(rb0.y), f2tf32(rb0.z), f2tf32(rb0.w));
            uint4 ub1 = make_uint4(f2tf32(rb1.x), f2tf32(rb1.y), f2tf32(rb1.z), f2tf32(rb1.w));
            *(uint4*)&As[lr][lc]     = ua0;
            *(uint4*)&As[lr][lc + 4] = ua1;
            *(uint4*)&Bs[lr][lc]     = ub0;
            *(uint4*)&Bs[lr][lc + 4] = ub1;
        }
        __syncthreads();

        if (k0 + 16 < kEnd) {   // prefetch next slab while mma runs
            ra0 = *(const float4*)(Ap + k0 + 16);
            ra1 = *(const float4*)(Ap + k0 + 20);
            if (bok) {
                rb0 = *(const float4*)(Bp + k0 + 16);
                rb1 = *(const float4*)(Bp + k0 + 20);
            }
        }

#pragma unroll
        for (int kk = 0; kk < 16; kk += 8) {
            unsigned af[2][4];
#pragma unroll
            for (int i = 0; i < 2; i++) {
                const int mrow = wm + i * 16;
                af[i][0] = As[mrow + r][kk + q];
                af[i][1] = As[mrow + r + 8][kk + q];
                af[i][2] = As[mrow + r][kk + q + 4];
                af[i][3] = As[mrow + r + 8][kk + q + 4];
            }
            unsigned bf[8][2];
#pragma unroll
            for (int j = 0; j < 8; j++) {
                const int nrow = wn + j * 8;
                bf[j][0] = Bs[nrow + r][kk + q];
                bf[j][1] = Bs[nrow + r][kk + q + 4];
            }
#pragma unroll
            for (int i = 0; i < 2; i++)
#pragma unroll
                for (int j = 0; j < 8; j++)
                    mma_m16n8k8_tf32(acc[i][j], af[i], bf[j]);
        }
    }

    // epilogue: c0,c1 at (row, col..col+1), c2,c3 at (row+8, col..col+1)
#pragma unroll
    for (int i = 0; i < 2; i++) {
        const int row = bm + wm + i * 16 + r;
#pragma unroll
        for (int j = 0; j < 8; j++) {
            const int col = bn + wn + j * 8 + q * 2;
            if (col < N) {
                *(float2*)&C[(size_t)row * ldc + col] =
                    make_float2(acc[i][j][0], acc[i][j][1]);
                *(float2*)&C[(size_t)(row + 8) * ldc + col] =
                    make_float2(acc[i][j][2], acc[i][j][3]);
            }
        }
    }
}

// ---------------------------------------------------------------------------
// FP32 fallback SGEMM (used only for the small dt-path GEMMs, kept in fp32 so
// delta keeps full precision before exp(delta*A)).
// EPI: 0 = plain store, 1 = softplus(x + bias[col]).
// ---------------------------------------------------------------------------
template<int EPI>
__global__ void __launch_bounds__(256, 2) sgemm128(
    const float* __restrict__ A, const float* __restrict__ B,
    float* __restrict__ C, int M, int N, int K,
    int lda, int ldb, int ldc, int kChunk,
    const float* __restrict__ bias)
{
    __shared__ float As[8][128];
    __shared__ float Bs[8][128];

    const int tid = threadIdx.x;
    const int bm = blockIdx.y * 128;
    const int bn = blockIdx.x * 128;
    int kBegin = blockIdx.z * kChunk;
    int kEnd   = kBegin + kChunk; if (kEnd > K) kEnd = K;
    C += (size_t)blockIdx.z * (size_t)M * (size_t)ldc;

    const int ar = tid >> 1;
    const int ac = (tid & 1) * 4;
    const int ty = tid >> 4;
    const int tx = tid & 15;

    float acc[8][8];
#pragma unroll
    for (int i = 0; i < 8; i++)
#pragma unroll
        for (int j = 0; j < 8; j++) acc[i][j] = 0.f;

    const float* Aptr = A + (size_t)(bm + ar) * lda + ac;
    const int brow = bn + ar;
    const float* Bptr = B + (size_t)brow * ldb + ac;
    const bool bvalid = (brow < N);

    for (int k0 = kBegin; k0 < kEnd; k0 += 8) {
        float4 av = *(const float4*)(Aptr + k0);
        float4 bv = make_float4(0.f, 0.f, 0.f, 0.f);
        if (bvalid) bv = *(const float4*)(Bptr + k0);

        __syncthreads();
        As[ac + 0][ar] = av.x; As[ac + 1][ar] = av.y;
        As[ac + 2][ar] = av.z; As[ac + 3][ar] = av.w;
        Bs[ac + 0][ar] = bv.x; Bs[ac + 1][ar] = bv.y;
        Bs[ac + 2][ar] = bv.z; Bs[ac + 3][ar] = bv.w;
        __syncthreads();

#pragma unroll
        for (int kk = 0; kk < 8; kk++) {
            float a[8], b[8];
#pragma unroll
            for (int i = 0; i < 8; i++) a[i] = As[kk][ty * 8 + i];
#pragma unroll
            for (int j = 0; j < 8; j++) b[j] = Bs[kk][tx * 8 + j];
#pragma unroll
            for (int i = 0; i < 8; i++)
#pragma unroll
                for (int j = 0; j < 8; j++)
                    acc[i][j] = fmaf(a[i], b[j], acc[i][j]);
        }
    }

#pragma unroll
    for (int i = 0; i < 8; i++) {
        const int row = bm + ty * 8 + i;
#pragma unroll
        for (int j = 0; j < 8; j++) {
            const int col = bn + tx * 8 + j;
            if (col < N) {
                float v = acc[i][j];
                if (EPI == 1) {
                    v += bias[col];
                    v = fmaxf(v, 0.f) + log1pf(__expf(-fabsf(v)));
                }
                C[(size_t)row * ldc + col] = v;
            }
        }
    }
}

// ---------------------------------------------------------------------------
// Depthwise causal conv (k=4) + bias + SiLU
// ---------------------------------------------------------------------------
__global__ void conv_silu_kernel(const float* __restrict__ xz,
                                 const float* __restrict__ cw,
                                 const float* __restrict__ cb,
                                 float* __restrict__ xsc)
{
    const int idx = blockIdx.x * blockDim.x + threadIdx.x;
    if (idx >= MROWS * DINNER) return;
    const int d = idx & (DINNER - 1);
    const int m = idx >> 11;
    const int l = m & (LSEQ - 1);

    const float w0 = cw[d * 4 + 0], w1 = cw[d * 4 + 1];
    const float w2 = cw[d * 4 + 2], w3 = cw[d * 4 + 3];
    const float* p = xz + (size_t)m * NXZ + d;

    float acc = cb[d] + w3 * p[0];
    if (l >= 1) acc = fmaf(w2, p[-NXZ],     acc);
    if (l >= 2) acc = fmaf(w1, p[-2 * NXZ], acc);
    if (l >= 3) acc = fmaf(w0, p[-3 * NXZ], acc);

    xsc[idx] = acc / (1.f + __expf(-acc));
}

// ---------------------------------------------------------------------------
// Split-K reductions
// ---------------------------------------------------------------------------
__global__ void reduce_dbc_kernel(const float* __restrict__ part,
                                  float* __restrict__ out)
{
    const int idx = blockIdx.x * blockDim.x + threadIdx.x;
    if (idx >= MROWS * NDBC) return;
    float s = 0.f;
#pragma unroll
    for (int j = 0; j < SPLITK_XPROJ; j++)
        s += part[(size_t)j * MROWS * NDBC + idx];
    out[idx] = s;
}

__global__ void reduce_out_kernel(const float* __restrict__ part,
                                  float* __restrict__ out)
{
    const int idx = blockIdx.x * blockDim.x + threadIdx.x;
    if (idx >= MROWS * DMODEL) return;
    out[idx] = part[idx] + part[(size_t)MROWS * DMODEL + idx];
}

// ---------------------------------------------------------------------------
// Selective scan: 16 lanes per (b,d) channel, one lane per state n.
// ---------------------------------------------------------------------------
__global__ void scan_kernel(const float* __restrict__ delta,
                            const float* __restrict__ xsc,
                            const float* __restrict__ dbc,
                            const float* __restrict__ xz,
                            const float* __restrict__ A_log,
                            const float* __restrict__ Dp,
                            float* __restrict__ y)
{
    const int gt = blockIdx.x * blockDim.x + threadIdx.x;
    const int ch = gt >> 4;
    if (ch >= BSZ * DINNER) return;
    const int n = threadIdx.x & 15;
    const int b = ch >> 11;
    const int d = ch & (DINNER - 1);

    const float An = -__expf(A_log[d * DSTATE + n]);
    const float Dd = Dp[d];

    const float* drow  = delta + (size_t)b * LSEQ * DINNER + d;
    const float* xrow  = xsc   + (size_t)b * LSEQ * DINNER + d;
    const float* zrow  = xz    + (size_t)b * LSEQ * NXZ + DINNER + d;
    const float* bcrow = dbc   + (size_t)b * LSEQ * NDBC;
    float*       yrow  = y     + (size_t)b * LSEQ * DINNER + d;

    float h = 0.f;
    for (int l = 0; l < LSEQ; l++) {
        const float dl = drow[(size_t)l * DINNER];
        const float xv = xrow[(size_t)l * DINNER];
        const float Bv = bcrow[l * NDBC + DTRANK + n];
        const float Cv = bcrow[l * NDBC + DTRANK + DSTATE + n];

        const float dA = __expf(dl * An);
        h = fmaf(dA, h, dl * xv * Bv);

        float part = h * Cv;
        part += __shfl_xor_sync(0xffffffffu, part, 8, 16);
        part += __shfl_xor_sync(0xffffffffu, part, 4, 16);
        part += __shfl_xor_sync(0xffffffffu, part, 2, 16);
        part += __shfl_xor_sync(0xffffffffu, part, 1, 16);

        if (n == 0) {
            const float yv = part + Dd * xv;
            const float zv = zrow[(size_t)l * NXZ];
            const float sz = zv / (1.f + __expf(-zv));
            yrow[(size_t)l * DINNER] = yv * sz;
        }
    }
}

// ---------------------------------------------------------------------------
// Launch
// ---------------------------------------------------------------------------
extern "C" void kernel_launch(void* const* d_in, const int* in_sizes, int n_in,
                              void* d_out, int out_size)
{
    const float* x         = (const float*)d_in[0];
    const float* in_proj_w = (const float*)d_in[1];
    const float* conv_w    = (const float*)d_in[2];
    const float* conv_b    = (const float*)d_in[3];
    const float* x_proj_w  = (const float*)d_in[4];
    const float* dt_proj_w = (const float*)d_in[5];
    const float* dt_proj_b = (const float*)d_in[6];
    const float* A_log     = (const float*)d_in[7];
    const float* Dvec      = (const float*)d_in[8];
    const float* out_proj_w= (const float*)d_in[9];
    float* out = (float*)d_out;

    float *xz, *xsc, *dbc_part, *dbc, *delta, *yb, *opart;
    cudaGetSymbolAddress((void**)&xz,       g_xz);
    cudaGetSymbolAddress((void**)&xsc,      g_xsc);
    cudaGetSymbolAddress((void**)&dbc_part, g_dbc_part);
    cudaGetSymbolAddress((void**)&dbc,      g_dbc);
    cudaGetSymbolAddress((void**)&delta,    g_delta);
    cudaGetSymbolAddress((void**)&yb,       g_y);
    cudaGetSymbolAddress((void**)&opart,    g_opart);

    // 1) xz = x @ in_proj_w^T  (2048 x 4096, K=1024)  — TF32 tensor cores
    {
        dim3 grid(NXZ / 128, MROWS / 128, 1);
        tgemm_tf32<<<grid, 256>>>(x, in_proj_w, xz,
                                  MROWS, NXZ, DMODEL,
                                  DMODEL, DMODEL, NXZ, DMODEL);
    }

    // 2) depthwise conv + bias + silu -> xsc
    {
        int n = MROWS * DINNER;
        conv_silu_kernel<<<(n + 255) / 256, 256>>>(xz, conv_w, conv_b, xsc);
    }

    // 3) dbc = xsc @ x_proj_w^T  (2048 x 96, K=2048), fp32, split-K=8
    {
        dim3 grid(1, MROWS / 128, SPLITK_XPROJ);
        sgemm128<0><<<grid, 256>>>(xsc, x_proj_w, dbc_part,
                                   MROWS, NDBC, DINNER,
                                   DINNER, DINNER, NDBC, DINNER / SPLITK_XPROJ,
                                   nullptr);
        int n = MROWS * NDBC;
        reduce_dbc_kernel<<<(n + 255) / 256, 256>>>(dbc_part, dbc);
    }

    // 4) delta = softplus(dbc[:, :64] @ dt_proj_w^T + dt_proj_b)  fp32
    {
        dim3 grid(DINNER / 128, MROWS / 128, 1);
        sgemm128<1><<<grid, 256>>>(dbc, dt_proj_w, delta,
                                   MROWS, DINNER, DTRANK,
                                   NDBC, DTRANK, DINNER, DTRANK, dt_proj_b);
    }

    // 5) selective scan -> yb
    {
        int threads = BSZ * DINNER * DSTATE;
        scan_kernel<<<threads / 256, 256>>>(delta, xsc, dbc, xz, A_log, Dvec, yb);
    }

    // 6) out = yb @ out_proj_w^T  (2048 x 1024, K=2048) — TF32, split-K=2
    {
        dim3 grid(DMODEL / 128, MROWS / 128, SPLITK_OPROJ);
        tgemm_tf32<<<grid, 256>>>(yb, out_proj_w, opart,
                                  MROWS, DMODEL, DINNER,
                                  DINNER, DINNER, DMODEL, DINNER / SPLITK_OPROJ);
        int n = MROWS * DMODEL;
        reduce_out_kernel<<<(n + 255) / 256, 256>>>(opart, out);
    }
}

// round 5
// speedup vs baseline: 1.6789x; 1.1502x over previous
#include <cuda_runtime.h>
#include <cuda_bf16.h>
#include <math.h>
#include <stdint.h>

// ---------------------------------------------------------------------------
// Problem constants
// ---------------------------------------------------------------------------
#define BSZ     2
#define LSEQ    1024
#define DMODEL  1024
#define DINNER  2048
#define DSTATE  16
#define DTRANK  64
#define MROWS   (BSZ * LSEQ)        // 2048
#define NXZ     (2 * DINNER)        // 4096
#define NDBC    (DTRANK + 2*DSTATE) // 96
#define SPLITK_XPROJ 8

// tcgen05 is only legal on arch-specific ("a") targets. The harness also
// compiles a plain compute_103/sm_103 pass; give that pass an mma.sync path.
#if defined(__CUDA_ARCH_FEAT_SM103_ALL) || defined(__CUDA_ARCH_FEAT_SM100_ALL) || defined(__CUDA_ARCH_FEAT_SM101_ALL)
#define HAS_TCGEN05 1
#else
#define HAS_TCGEN05 0
#endif

// ---------------------------------------------------------------------------
// Scratch (static device memory; no allocations allowed)
// ---------------------------------------------------------------------------
__device__ float g_xz[MROWS * NXZ];                       // (xs | z)
__device__ float g_xsc[MROWS * DINNER];                   // conv+silu output
__device__ float g_dbc_part[SPLITK_XPROJ * MROWS * NDBC];
__device__ float g_dbc[MROWS * NDBC];
__device__ float g_delta[MROWS * DINNER];
__device__ float g_y[MROWS * DINNER];                     // gated scan output

// ---------------------------------------------------------------------------
// Small PTX helpers
// ---------------------------------------------------------------------------
__device__ __forceinline__ unsigned f2tf32(float x) {
    unsigned r;
    asm("cvt.rna.tf32.f32 %0, %1;" : "=r"(r) : "f"(x));
    return r;
}

__device__ __forceinline__ uint32_t smem_u32(const void* p) {
    uint32_t a;
    asm("{ .reg .u64 t; cvta.to.shared.u64 t, %1; cvt.u32.u64 %0, t; }"
        : "=r"(a) : "l"(p));
    return a;
}

#if HAS_TCGEN05
__device__ __forceinline__ uint32_t elect_one() {
    uint32_t pred;
    asm volatile("{\n .reg .pred p;\n elect.sync _|p, 0xFFFFFFFF;\n"
                 " selp.b32 %0, 1, 0, p;\n}" : "=r"(pred));
    return pred;
}

__device__ __forceinline__ void mbar_init(uint32_t addr, uint32_t cnt) {
    asm volatile("mbarrier.init.shared.b64 [%0], %1;" :: "r"(addr), "r"(cnt) : "memory");
}
__device__ __forceinline__ void mbar_inval(uint32_t addr) {
    asm volatile("mbarrier.inval.shared.b64 [%0];" :: "r"(addr) : "memory");
}
__device__ __forceinline__ void mbar_wait_parity(uint32_t addr, uint32_t parity) {
    asm volatile(
        "{\n .reg .pred P;\n"
        "WAIT_%=:\n"
        " mbarrier.try_wait.parity.acquire.cta.shared::cta.b64 P, [%0], %1, 0x989680;\n"
        " @P bra.uni DONE_%=;\n"
        " bra.uni WAIT_%=;\n"
        "DONE_%=:\n}"
        :: "r"(addr), "r"(parity) : "memory");
}

// 64-bit SMEM matrix descriptor: SW128, Blackwell, LBO=1, SBO=64
__device__ __forceinline__ uint64_t smem_desc_sw128(uint32_t addr) {
    const uint64_t base =
        (uint64_t(2) << 61) | (uint64_t(1) << 46) |
        (uint64_t(64) << 32) | (uint64_t(1) << 16);
    return base | ((uint64_t)(addr >> 4) & 0x3FFF);
}

__device__ __forceinline__ void mma_tf32_ss(uint32_t d_tmem, uint64_t a_desc,
                                            uint64_t b_desc, uint32_t idesc,
                                            uint32_t enable) {
    asm volatile(
        "{\n .reg .pred p;\n"
        " setp.ne.u32 p, %5, 0;\n"
        " tcgen05.mma.cta_group::1.kind::tf32 [%0], %1, %2, %3, {%4, %4, %4, %4}, p;\n"
        "}"
        :: "r"(d_tmem), "l"(a_desc), "l"(b_desc), "r"(idesc), "r"(0u), "r"(enable)
        : "memory");
}
#else
__device__ __forceinline__ void mma_m16n8k8_tf32(float c[4], const unsigned a[4],
                                                 const unsigned b[2]) {
    asm volatile(
        "mma.sync.aligned.m16n8k8.row.col.f32.tf32.tf32.f32 "
        "{%0,%1,%2,%3}, {%4,%5,%6,%7}, {%8,%9}, {%0,%1,%2,%3};\n"
        : "+f"(c[0]), "+f"(c[1]), "+f"(c[2]), "+f"(c[3])
        : "r"(a[0]), "r"(a[1]), "r"(a[2]), "r"(a[3]), "r"(b[0]), "r"(b[1]));
}
#endif

// ---------------------------------------------------------------------------
// TF32 GEMM: C[m,n] = sum_k A[m,k] * B[n,k]  (both K-contiguous).
// CTA tile 128x128, 128 threads. tcgen05 path on sm_103a; mma.sync fallback
// on the generic target (correct, slower — not used at runtime on GB300).
// Requires M%128==0, N%128==0, K%32==0, lda/ldb%4==0.
// ---------------------------------------------------------------------------
__global__ void __launch_bounds__(128) tgemm_tc(
    const float* __restrict__ A, const float* __restrict__ B,
    float* __restrict__ C, int K, int lda, int ldb, int ldc)
{
    __shared__ __align__(1024) unsigned As[128 * 32];   // 16 KB
    __shared__ __align__(1024) unsigned Bs[128 * 32];   // 16 KB
#if HAS_TCGEN05
    __shared__ __align__(8) unsigned long long mbar_s;
    __shared__ unsigned tptr_s;
#endif

    const int tid = threadIdx.x;
    const int wid = tid >> 5, lane = tid & 31;
    const int bm = blockIdx.y * 128;
    const int bn = blockIdx.x * 128;

    // loader mapping: thread covers rows r0 + 16*i, float4 column c4
    const int r0 = tid >> 3;      // 0..15
    const int c4 = tid & 7;       // 0..7  (16B groups within 128B row)

    const float* Ap = A + (size_t)(bm + r0) * lda + c4 * 4;
    const float* Bp = B + (size_t)(bn + r0) * ldb + c4 * 4;
    const int nch = K / 32;

#if HAS_TCGEN05
    const uint32_t s_as   = smem_u32(As);
    const uint32_t s_bs   = smem_u32(Bs);
    const uint32_t s_mbar = smem_u32(&mbar_s);
    const uint32_t s_tptr = smem_u32(&tptr_s);

    // TMEM alloc (warp 0), 128 columns for D
    if (wid == 0) {
        asm volatile("tcgen05.alloc.cta_group::1.sync.aligned.shared::cta.b32 [%0], %1;"
                     :: "r"(s_tptr), "r"(128u) : "memory");
        asm volatile("tcgen05.relinquish_alloc_permit.cta_group::1.sync.aligned;");
    }
    if (tid == 0) mbar_init(s_mbar, 1);
    __syncthreads();

    uint32_t tmem;
    asm volatile("ld.shared.b32 %0, [%1];" : "=r"(tmem) : "r"(s_tptr));

    // idesc: cfmt=F32(1)@[4:5], afmt=TF32(2)@[7:9], bfmt=TF32(2)@[10:12],
    //        N/8 @[17:22], M/16 @[24:28]
    const uint32_t idesc = (1u << 4) | (2u << 7) | (2u << 10) |
                           ((128u / 8) << 17) | ((128u / 16) << 24);

    const uint64_t adesc0 = smem_desc_sw128(s_as);
    const uint64_t bdesc0 = smem_desc_sw128(s_bs);

    for (int c = 0; c < nch; c++) {
        if (c > 0) mbar_wait_parity(s_mbar, (c - 1) & 1); // MMA done reading smem

#pragma unroll
        for (int i = 0; i < 8; i++) {
            const int row = r0 + i * 16;
            float4 av = *(const float4*)(Ap + (size_t)(i * 16) * lda + c * 32);
            float4 bv = *(const float4*)(Bp + (size_t)(i * 16) * ldb + c * 32);
            unsigned off = row * 128 + c4 * 16;
            unsigned sw = off ^ ((off >> 3) & 0x70);
            *(uint4*)((char*)As + sw) =
                make_uint4(f2tf32(av.x), f2tf32(av.y), f2tf32(av.z), f2tf32(av.w));
            *(uint4*)((char*)Bs + sw) =
                make_uint4(f2tf32(bv.x), f2tf32(bv.y), f2tf32(bv.z), f2tf32(bv.w));
        }
        asm volatile("fence.proxy.async.shared::cta;" ::: "memory");
        __syncthreads();

        if (wid == 0 && elect_one()) {
#pragma unroll
            for (int ks = 0; ks < 4; ks++) {
                mma_tf32_ss(tmem, adesc0 + ks * 2, bdesc0 + ks * 2, idesc,
                            (c > 0 || ks > 0) ? 1u : 0u);
            }
            asm volatile(
                "tcgen05.commit.cta_group::1.mbarrier::arrive::one.shared::cluster.b64 [%0];"
                :: "r"(s_mbar) : "memory");
        }
    }

    // wait for last chunk's MMA, then read D from TMEM
    mbar_wait_parity(s_mbar, (nch - 1) & 1);
    asm volatile("tcgen05.fence::after_thread_sync;" ::: "memory");

    const int row = bm + wid * 32 + lane;
    float* Crow = C + (size_t)row * ldc + bn;
#pragma unroll
    for (int g = 0; g < 4; g++) {
        uint32_t d[32];
        asm volatile(
            "tcgen05.ld.sync.aligned.32x32b.x32.b32 "
            "{%0,%1,%2,%3,%4,%5,%6,%7,%8,%9,%10,%11,%12,%13,%14,%15,"
            "%16,%17,%18,%19,%20,%21,%22,%23,%24,%25,%26,%27,%28,%29,%30,%31}, [%32];"
            : "=r"(d[0]), "=r"(d[1]), "=r"(d[2]), "=r"(d[3]),
              "=r"(d[4]), "=r"(d[5]), "=r"(d[6]), "=r"(d[7]),
              "=r"(d[8]), "=r"(d[9]), "=r"(d[10]), "=r"(d[11]),
              "=r"(d[12]), "=r"(d[13]), "=r"(d[14]), "=r"(d[15]),
              "=r"(d[16]), "=r"(d[17]), "=r"(d[18]), "=r"(d[19]),
              "=r"(d[20]), "=r"(d[21]), "=r"(d[22]), "=r"(d[23]),
              "=r"(d[24]), "=r"(d[25]), "=r"(d[26]), "=r"(d[27]),
              "=r"(d[28]), "=r"(d[29]), "=r"(d[30]), "=r"(d[31])
            : "r"(tmem + g * 32));
        asm volatile("tcgen05.wait::ld.sync.aligned;" ::: "memory");
#pragma unroll
        for (int v = 0; v < 8; v++) {
            *(float4*)(Crow + g * 32 + v * 4) = make_float4(
                __uint_as_float(d[v * 4 + 0]), __uint_as_float(d[v * 4 + 1]),
                __uint_as_float(d[v * 4 + 2]), __uint_as_float(d[v * 4 + 3]));
        }
    }

    __syncthreads();
    if (tid == 0) mbar_inval(s_mbar);
    __syncthreads();
    if (wid == 0) {
        asm volatile("tcgen05.dealloc.cta_group::1.sync.aligned.b32 %0, %1;"
                     :: "r"(tmem), "r"(128u));
    }
#else
    // ------------------ mma.sync fallback (generic sm_103 pass) ------------
    // 4 warps; warp w covers M rows [w*32, w*32+32), all 128 N columns.
    const int wm = wid * 32;
    const int q = lane & 3;           // 0..3
    const int r = lane >> 2;          // 0..7

    float acc[2][16][4];
#pragma unroll
    for (int i = 0; i < 2; i++)
#pragma unroll
        for (int j = 0; j < 16; j++)
#pragma unroll
            for (int t = 0; t < 4; t++) acc[i][j][t] = 0.f;

    for (int c = 0; c < nch; c++) {
        __syncthreads();
#pragma unroll
        for (int i = 0; i < 8; i++) {
            const int row = r0 + i * 16;
            float4 av = *(const float4*)(Ap + (size_t)(i * 16) * lda + c * 32);
            float4 bv = *(const float4*)(Bp + (size_t)(i * 16) * ldb + c * 32);
            *(uint4*)&As[row * 32 + c4 * 4] =
                make_uint4(f2tf32(av.x), f2tf32(av.y), f2tf32(av.z), f2tf32(av.w));
            *(uint4*)&Bs[row * 32 + c4 * 4] =
                make_uint4(f2tf32(bv.x), f2tf32(bv.y), f2tf32(bv.z), f2tf32(bv.w));
        }
        __syncthreads();

#pragma unroll
        for (int kk = 0; kk < 32; kk += 8) {
            unsigned af[2][4];
#pragma unroll
            for (int i = 0; i < 2; i++) {
                const int mrow = wm + i * 16;
                af[i][0] = As[(mrow + r) * 32 + kk + q];
                af[i][1] = As[(mrow + r + 8) * 32 + kk + q];
                af[i][2] = As[(mrow + r) * 32 + kk + q + 4];
                af[i][3] = As[(mrow + r + 8) * 32 + kk + q + 4];
            }
#pragma unroll
            for (int j = 0; j < 16; j++) {
                unsigned bf[2];
                bf[0] = Bs[(j * 8 + r) * 32 + kk + q];
                bf[1] = Bs[(j * 8 + r) * 32 + kk + q + 4];
#pragma unroll
                for (int i = 0; i < 2; i++)
                    mma_m16n8k8_tf32(acc[i][j], af[i], bf);
            }
        }
    }

#pragma unroll
    for (int i = 0; i < 2; i++) {
        const int row = bm + wm + i * 16 + r;
#pragma unroll
        for (int j = 0; j < 16; j++) {
            const int col = bn + j * 8 + q * 2;
            *(float2*)&C[(size_t)row * ldc + col] =
                make_float2(acc[i][j][0], acc[i][j][1]);
            *(float2*)&C[(size_t)(row + 8) * ldc + col] =
                make_float2(acc[i][j][2], acc[i][j][3]);
        }
    }
#endif
}

// ---------------------------------------------------------------------------
// FP32 SGEMM for the small dt-path GEMMs (precision of delta before exp).
// EPI: 0 = plain store, 1 = softplus(x + bias[col]).
// ---------------------------------------------------------------------------
template<int EPI>
__global__ void __launch_bounds__(256, 2) sgemm128(
    const float* __restrict__ A, const float* __restrict__ B,
    float* __restrict__ C, int M, int N, int K,
    int lda, int ldb, int ldc, int kChunk,
    const float* __restrict__ bias)
{
    __shared__ float As[8][128];
    __shared__ float Bs[8][128];

    const int tid = threadIdx.x;
    const int bm = blockIdx.y * 128;
    const int bn = blockIdx.x * 128;
    int kBegin = blockIdx.z * kChunk;
    int kEnd   = kBegin + kChunk; if (kEnd > K) kEnd = K;
    C += (size_t)blockIdx.z * (size_t)M * (size_t)ldc;

    const int ar = tid >> 1;
    const int ac = (tid & 1) * 4;
    const int ty = tid >> 4;
    const int tx = tid & 15;

    float acc[8][8];
#pragma unroll
    for (int i = 0; i < 8; i++)
#pragma unroll
        for (int j = 0; j < 8; j++) acc[i][j] = 0.f;

    const float* Aptr = A + (size_t)(bm + ar) * lda + ac;
    const int brow = bn + ar;
    const float* Bptr = B + (size_t)brow * ldb + ac;
    const bool bvalid = (brow < N);

    for (int k0 = kBegin; k0 < kEnd; k0 += 8) {
        float4 av = *(const float4*)(Aptr + k0);
        float4 bv = make_float4(0.f, 0.f, 0.f, 0.f);
        if (bvalid) bv = *(const float4*)(Bptr + k0);

        __syncthreads();
        As[ac + 0][ar] = av.x; As[ac + 1][ar] = av.y;
        As[ac + 2][ar] = av.z; As[ac + 3][ar] = av.w;
        Bs[ac + 0][ar] = bv.x; Bs[ac + 1][ar] = bv.y;
        Bs[ac + 2][ar] = bv.z; Bs[ac + 3][ar] = bv.w;
        __syncthreads();

#pragma unroll
        for (int kk = 0; kk < 8; kk++) {
            float a[8], b[8];
#pragma unroll
            for (int i = 0; i < 8; i++) a[i] = As[kk][ty * 8 + i];
#pragma unroll
            for (int j = 0; j < 8; j++) b[j] = Bs[kk][tx * 8 + j];
#pragma unroll
            for (int i = 0; i < 8; i++)
#pragma unroll
                for (int j = 0; j < 8; j++)
                    acc[i][j] = fmaf(a[i], b[j], acc[i][j]);
        }
    }

#pragma unroll
    for (int i = 0; i < 8; i++) {
        const int row = bm + ty * 8 + i;
#pragma unroll
        for (int j = 0; j < 8; j++) {
            const int col = bn + tx * 8 + j;
            if (col < N) {
                float v = acc[i][j];
                if (EPI == 1) {
                    v += bias[col];
                    v = fmaxf(v, 0.f) + log1pf(__expf(-fabsf(v)));
                }
                C[(size_t)row * ldc + col] = v;
            }
        }
    }
}

// ---------------------------------------------------------------------------
// Depthwise causal conv (k=4) + bias + SiLU
// ---------------------------------------------------------------------------
__global__ void conv_silu_kernel(const float* __restrict__ xz,
                                 const float* __restrict__ cw,
                                 const float* __restrict__ cb,
                                 float* __restrict__ xsc)
{
    const int idx = blockIdx.x * blockDim.x + threadIdx.x;
    if (idx >= MROWS * DINNER) return;
    const int d = idx & (DINNER - 1);
    const int m = idx >> 11;
    const int l = m & (LSEQ - 1);

    const float w0 = cw[d * 4 + 0], w1 = cw[d * 4 + 1];
    const float w2 = cw[d * 4 + 2], w3 = cw[d * 4 + 3];
    const float* p = xz + (size_t)m * NXZ + d;

    float acc = cb[d] + w3 * p[0];
    if (l >= 1) acc = fmaf(w2, p[-NXZ],     acc);
    if (l >= 2) acc = fmaf(w1, p[-2 * NXZ], acc);
    if (l >= 3) acc = fmaf(w0, p[-3 * NXZ], acc);

    xsc[idx] = acc / (1.f + __expf(-acc));
}

// ---------------------------------------------------------------------------
// Split-K reduction for x_proj
// ---------------------------------------------------------------------------
__global__ void reduce_dbc_kernel(const float* __restrict__ part,
                                  float* __restrict__ out)
{
    const int idx = blockIdx.x * blockDim.x + threadIdx.x;
    if (idx >= MROWS * NDBC) return;
    float s = 0.f;
#pragma unroll
    for (int j = 0; j < SPLITK_XPROJ; j++)
        s += part[(size_t)j * MROWS * NDBC + idx];
    out[idx] = s;
}

// ---------------------------------------------------------------------------
// Selective scan: 16 lanes per (b,d) channel, one lane per state n.
// ---------------------------------------------------------------------------
__global__ void scan_kernel(const float* __restrict__ delta,
                            const float* __restrict__ xsc,
                            const float* __restrict__ dbc,
                            const float* __restrict__ xz,
                            const float* __restrict__ A_log,
                            const float* __restrict__ Dp,
                            float* __restrict__ y)
{
    const int gt = blockIdx.x * blockDim.x + threadIdx.x;
    const int ch = gt >> 4;
    if (ch >= BSZ * DINNER) return;
    const int n = threadIdx.x & 15;
    const int b = ch >> 11;
    const int d = ch & (DINNER - 1);

    const float An = -__expf(A_log[d * DSTATE + n]);
    const float Dd = Dp[d];

    const float* drow  = delta + (size_t)b * LSEQ * DINNER + d;
    const float* xrow  = xsc   + (size_t)b * LSEQ * DINNER + d;
    const float* zrow  = xz    + (size_t)b * LSEQ * NXZ + DINNER + d;
    const float* bcrow = dbc   + (size_t)b * LSEQ * NDBC;
    float*       yrow  = y     + (size_t)b * LSEQ * DINNER + d;

    float h = 0.f;
    for (int l = 0; l < LSEQ; l++) {
        const float dl = drow[(size_t)l * DINNER];
        const float xv = xrow[(size_t)l * DINNER];
        const float Bv = bcrow[l * NDBC + DTRANK + n];
        const float Cv = bcrow[l * NDBC + DTRANK + DSTATE + n];

        const float dA = __expf(dl * An);
        h = fmaf(dA, h, dl * xv * Bv);

        float part = h * Cv;
        part += __shfl_xor_sync(0xffffffffu, part, 8, 16);
        part += __shfl_xor_sync(0xffffffffu, part, 4, 16);
        part += __shfl_xor_sync(0xffffffffu, part, 2, 16);
        part += __shfl_xor_sync(0xffffffffu, part, 1, 16);

        if (n == 0) {
            const float yv = part + Dd * xv;
            const float zv = zrow[(size_t)l * NXZ];
            const float sz = zv / (1.f + __expf(-zv));
            yrow[(size_t)l * DINNER] = yv * sz;
        }
    }
}

// ---------------------------------------------------------------------------
// Launch
// ---------------------------------------------------------------------------
extern "C" void kernel_launch(void* const* d_in, const int* in_sizes, int n_in,
                              void* d_out, int out_size)
{
    const float* x         = (const float*)d_in[0];
    const float* in_proj_w = (const float*)d_in[1];
    const float* conv_w    = (const float*)d_in[2];
    const float* conv_b    = (const float*)d_in[3];
    const float* x_proj_w  = (const float*)d_in[4];
    const float* dt_proj_w = (const float*)d_in[5];
    const float* dt_proj_b = (const float*)d_in[6];
    const float* A_log     = (const float*)d_in[7];
    const float* Dvec      = (const float*)d_in[8];
    const float* out_proj_w= (const float*)d_in[9];
    float* out = (float*)d_out;

    float *xz, *xsc, *dbc_part, *dbc, *delta, *yb;
    cudaGetSymbolAddress((void**)&xz,       g_xz);
    cudaGetSymbolAddress((void**)&xsc,      g_xsc);
    cudaGetSymbolAddress((void**)&dbc_part, g_dbc_part);
    cudaGetSymbolAddress((void**)&dbc,      g_dbc);
    cudaGetSymbolAddress((void**)&delta,    g_delta);
    cudaGetSymbolAddress((void**)&yb,       g_y);

    // 1) xz = x @ in_proj_w^T  (2048 x 4096, K=1024)  — tcgen05 TF32
    {
        dim3 grid(NXZ / 128, MROWS / 128);
        tgemm_tc<<<grid, 128>>>(x, in_proj_w, xz, DMODEL, DMODEL, DMODEL, NXZ);
    }

    // 2) depthwise conv + bias + silu -> xsc
    {
        int n = MROWS * DINNER;
        conv_silu_kernel<<<(n + 255) / 256, 256>>>(xz, conv_w, conv_b, xsc);
    }

    // 3) dbc = xsc @ x_proj_w^T  (2048 x 96, K=2048), fp32, split-K=8
    {
        dim3 grid(1, MROWS / 128, SPLITK_XPROJ);
        sgemm128<0><<<grid, 256>>>(xsc, x_proj_w, dbc_part,
                                   MROWS, NDBC, DINNER,
                                   DINNER, DINNER, NDBC, DINNER / SPLITK_XPROJ,
                                   nullptr);
        int n = MROWS * NDBC;
        reduce_dbc_kernel<<<(n + 255) / 256, 256>>>(dbc_part, dbc);
    }

    // 4) delta = softplus(dbc[:, :64] @ dt_proj_w^T + dt_proj_b)  fp32
    {
        dim3 grid(DINNER / 128, MROWS / 128, 1);
        sgemm128<1><<<grid, 256>>>(dbc, dt_proj_w, delta,
                                   MROWS, DINNER, DTRANK,
                                   NDBC, DTRANK, DINNER, DTRANK, dt_proj_b);
    }

    // 5) selective scan -> yb
    {
        int threads = BSZ * DINNER * DSTATE;
        scan_kernel<<<threads / 256, 256>>>(delta, xsc, dbc, xz, A_log, Dvec, yb);
    }

    // 6) out = yb @ out_proj_w^T  (2048 x 1024, K=2048) — tcgen05 TF32, direct
    {
        dim3 grid(DMODEL / 128, MROWS / 128);
        tgemm_tc<<<grid, 128>>>(yb, out_proj_w, out, DINNER, DINNER, DINNER, DMODEL);
    }
}